// round 15
// baseline (speedup 1.0000x reference)
#include <cuda_runtime.h>
#include <cstdint>

#define H_ 128
#define W_ 128
#define HW 16384
#define CIN 384
#define CQ 384
#define C3 1152
#define NH 6
#define HD 64
#define NB 4
#define KDIM 384          // K for both GEMMs
#define NSLAB 12          // 384 / 32

// Scratch (no allocation allowed). RULE: device globals are referenced ONLY
// from device code — never passed as kernel args from host (ATS makes the
// host shadow symbol silently writable -> zero-filled device arrays).
__device__ float    g_qkv   [(size_t)NB * C3 * HW];   // qkv [b][c3][hw]
__device__ float    g_attnT [(size_t)NB * HW * CQ];   // branch-1 out (fp32)
__device__ uint16_t g_xb_hi [(size_t)NB * HW * CIN];  // x^T bf16 hi [b][hw][c]
__device__ uint16_t g_xb_lo [(size_t)NB * HW * CIN];
__device__ uint16_t g_at_hi [(size_t)NB * HW * CQ];   // (attn1+attn2) bf16 hi
__device__ uint16_t g_at_lo [(size_t)NB * HW * CQ];
__device__ uint16_t g_wq_hi [C3 * KDIM];
__device__ uint16_t g_wq_lo [C3 * KDIM];
__device__ uint16_t g_wh_hi [CQ * KDIM];
__device__ uint16_t g_wh_lo [CQ * KDIM];

// ===========================================================================
// helpers (baseline PTX, valid in every sm_103 gencode pass)
// ===========================================================================
static __device__ __forceinline__ void mma_bf16(
    float* d, const uint32_t* a, const uint32_t* b)
{
    asm volatile(
        "mma.sync.aligned.m16n8k16.row.col.f32.bf16.bf16.f32 "
        "{%0,%1,%2,%3}, {%4,%5,%6,%7}, {%8,%9}, {%0,%1,%2,%3};"
        : "+f"(d[0]), "+f"(d[1]), "+f"(d[2]), "+f"(d[3])
        : "r"(a[0]), "r"(a[1]), "r"(a[2]), "r"(a[3]),
          "r"(b[0]), "r"(b[1]));
}

static __device__ __forceinline__ void ldm4(uint32_t* r, uint32_t addr)
{
    asm volatile(
        "ldmatrix.sync.aligned.m8n8.x4.shared.b16 {%0,%1,%2,%3}, [%4];"
        : "=r"(r[0]), "=r"(r[1]), "=r"(r[2]), "=r"(r[3])
        : "r"(addr));
}

static __device__ __forceinline__ uint32_t smem_u32(const void* p) {
    uint32_t a;
    asm("{ .reg .u64 t; cvta.to.shared.u64 t, %1; cvt.u32.u64 %0, t; }"
        : "=r"(a) : "l"(p));
    return a;
}

static __device__ __forceinline__ uint32_t pack_bf16x2(float lo, float hi) {
    uint32_t r;
    asm("cvt.rn.bf16x2.f32 %0, %1, %2;" : "=r"(r) : "f"(hi), "f"(lo));
    return r;
}
static __device__ __forceinline__ float bf16lo_f(uint32_t r) {
    return __uint_as_float(r << 16);
}
static __device__ __forceinline__ float bf16hi_f(uint32_t r) {
    return __uint_as_float(r & 0xFFFF0000u);
}

// split 8 consecutive floats into bf16 hi/lo uint4s
static __device__ __forceinline__ void split8(const float* f, uint4& hi, uint4& lo)
{
    hi.x = pack_bf16x2(f[0], f[1]);
    hi.y = pack_bf16x2(f[2], f[3]);
    hi.z = pack_bf16x2(f[4], f[5]);
    hi.w = pack_bf16x2(f[6], f[7]);
    lo.x = pack_bf16x2(f[0] - bf16lo_f(hi.x), f[1] - bf16hi_f(hi.x));
    lo.y = pack_bf16x2(f[2] - bf16lo_f(hi.y), f[3] - bf16hi_f(hi.y));
    lo.z = pack_bf16x2(f[4] - bf16lo_f(hi.z), f[5] - bf16hi_f(hi.z));
    lo.w = pack_bf16x2(f[6] - bf16lo_f(hi.w), f[7] - bf16hi_f(hi.w));
}

#define CP_ASYNC16(sa, gp) \
    asm volatile("cp.async.cg.shared.global [%0], [%1], 16;" :: "r"(sa), "l"(gp))
#define CP_COMMIT() asm volatile("cp.async.commit_group;" ::: "memory")
#define CP_WAIT(n)  asm volatile("cp.async.wait_group %0;" :: "n"(n) : "memory")

// ===========================================================================
// prep: split weights into bf16 hi/lo (device-side target selection)
// ===========================================================================
__global__ __launch_bounds__(256) void prep_w_kernel(
    const float* __restrict__ w, int which, int n4)
{
    uint16_t* hi = which ? g_wh_hi : g_wq_hi;
    uint16_t* lo = which ? g_wh_lo : g_wq_lo;
    int i = blockIdx.x * 256 + threadIdx.x;
    if (i >= n4) return;
    float4 v = ((const float4*)w)[i];
    uint2 h, l;
    h.x = pack_bf16x2(v.x, v.y);
    h.y = pack_bf16x2(v.z, v.w);
    l.x = pack_bf16x2(v.x - bf16lo_f(h.x), v.y - bf16hi_f(h.x));
    l.y = pack_bf16x2(v.z - bf16lo_f(h.y), v.w - bf16hi_f(h.y));
    ((uint2*)hi)[i] = h;
    ((uint2*)lo)[i] = l;
}

// ===========================================================================
// Transpose + split: x[b][C][HW] -> g_xb_hi/lo [b][hw][c]
// ===========================================================================
__global__ __launch_bounds__(256) void transpose_x_kernel(const float* __restrict__ x)
{
    __shared__ float sm[32][33];
    const int z = blockIdx.z;
    const int hw0 = blockIdx.x * 32, c0 = blockIdx.y * 32;
    const float* xz = x + (size_t)z * CIN * HW;
    uint16_t* th = g_xb_hi + (size_t)z * HW * CIN;
    uint16_t* tl = g_xb_lo + (size_t)z * HW * CIN;
    const int t = threadIdx.x;
    const int tx = t & 31, ty = t >> 5;

    #pragma unroll
    for (int i = 0; i < 4; i++)
        sm[ty + 8 * i][tx] = xz[(size_t)(c0 + ty + 8 * i) * HW + hw0 + tx];
    __syncthreads();

    {
        int h = t >> 3, cp = (t & 7) * 4;
        float v0 = sm[cp + 0][h], v1 = sm[cp + 1][h];
        float v2 = sm[cp + 2][h], v3 = sm[cp + 3][h];
        uint2 hi, lo;
        hi.x = pack_bf16x2(v0, v1);
        hi.y = pack_bf16x2(v2, v3);
        lo.x = pack_bf16x2(v0 - bf16lo_f(hi.x), v1 - bf16hi_f(hi.x));
        lo.y = pack_bf16x2(v2 - bf16lo_f(hi.y), v3 - bf16hi_f(hi.y));
        size_t off = (size_t)(hw0 + h) * CIN + c0 + cp;
        *(uint2*)&th[off] = hi;
        *(uint2*)&tl[off] = lo;
    }
}

// ===========================================================================
// bf16x3-split tensor-core GEMM (round-13 exact).
// ===========================================================================
#define RSB   64
#define ABUF  8192
#define SMBUF 32768
#define NSTG  3
#define GEMM_SMEM (NSTG * SMBUF)

__global__ __launch_bounds__(256, 2) void gemm_bf16x3_kernel(
    const float* __restrict__ bias, float* __restrict__ Cext, int mode)
{
    extern __shared__ char dynsm[];
    const uint32_t sbase = smem_u32(dynsm);

    const int tid  = threadIdx.x;
    const int lane = tid & 31;
    const int wid  = tid >> 5;
    const int m0 = blockIdx.x * 128;
    const int n0 = blockIdx.y * 128;
    const int z  = blockIdx.z;

    const uint16_t* Ahi = (mode == 0) ? g_wq_hi : g_wh_hi;
    const uint16_t* Alo = (mode == 0) ? g_wq_lo : g_wh_lo;
    const uint16_t* Bhi = ((mode == 0) ? g_xb_hi : g_at_hi) + (size_t)z * HW * KDIM;
    const uint16_t* Blo = ((mode == 0) ? g_xb_lo : g_at_lo) + (size_t)z * HW * KDIM;
    float* C = (mode == 0) ? (g_qkv + (size_t)z * C3 * HW)
                           : (Cext  + (size_t)z * CQ * HW);

    const uint16_t* gptr[8];
    uint32_t soff[8];
    #pragma unroll
    for (int i = 0; i < 8; i++) {
        int id  = i * 256 + tid;
        int arr = id >> 9;
        int idx = id & 511;
        int r   = idx >> 2;
        int q   = idx & 3;
        const uint16_t* base =
            (arr == 0) ? Ahi + (size_t)(m0 + r) * KDIM :
            (arr == 1) ? Alo + (size_t)(m0 + r) * KDIM :
            (arr == 2) ? Bhi + (size_t)(n0 + r) * KDIM :
                         Blo + (size_t)(n0 + r) * KDIM;
        gptr[i] = base + q * 8;
        soff[i] = (uint32_t)(arr * ABUF + r * RSB + ((q ^ ((r >> 1) & 3)) * 16));
    }

#define ISSUE_SLAB(k0, bufOff) do {                                           \
        _Pragma("unroll")                                                     \
        for (int i = 0; i < 8; i++)                                           \
            CP_ASYNC16(sbase + (bufOff) + soff[i], gptr[i] + (k0));           \
        CP_COMMIT();                                                          \
    } while (0)

    const int mbase = (wid & 3) * 32;
    const int nbase = (wid >> 2) * 64;
    const int row_a = (lane & 7) + ((lane >> 3) & 1) * 8;
    const int qa_hi = lane >> 4;
    const int row_b = (lane & 7) + (lane >> 4) * 8;
    const int qb_hi = (lane >> 3) & 1;

    float acc[2][8][4];
    #pragma unroll
    for (int i = 0; i < 2; i++)
        #pragma unroll
        for (int j = 0; j < 8; j++)
            #pragma unroll
            for (int r = 0; r < 4; r++) acc[i][j][r] = 0.f;

    ISSUE_SLAB(0, 0);
    ISSUE_SLAB(32, SMBUF);

    for (int s = 0; s < NSLAB; s++) {
        if (s + 1 < NSLAB) CP_WAIT(1);
        else               CP_WAIT(0);
        __syncthreads();
        if (s + 2 < NSLAB) ISSUE_SLAB((s + 2) * 32, ((s + 2) % NSTG) * SMBUF);

        const uint32_t base = sbase + (s % NSTG) * SMBUF;
        #pragma unroll
        for (int kc = 0; kc < 2; kc++) {
            uint32_t af[2][4], al[2][4], bf[4][4];
            #pragma unroll
            for (int i = 0; i < 2; i++) {
                int rw = mbase + i * 16 + row_a;
                uint32_t c = (uint32_t)((2 * kc + qa_hi) ^ ((rw >> 1) & 3));
                uint32_t ra_ = base + rw * RSB + c * 16;
                ldm4(af[i], ra_);
                ldm4(al[i], ra_ + ABUF);
            }
            #pragma unroll
            for (int p = 0; p < 4; p++) {
                int rw = nbase + p * 16 + row_b;
                uint32_t c = (uint32_t)((2 * kc + qb_hi) ^ ((rw >> 1) & 3));
                ldm4(bf[p], base + 2 * ABUF + rw * RSB + c * 16);
            }
            #pragma unroll
            for (int i = 0; i < 2; i++)
                #pragma unroll
                for (int j = 0; j < 8; j++)
                    mma_bf16(acc[i][j], af[i], &bf[j >> 1][(j & 1) * 2]);
            #pragma unroll
            for (int i = 0; i < 2; i++)
                #pragma unroll
                for (int j = 0; j < 8; j++)
                    mma_bf16(acc[i][j], al[i], &bf[j >> 1][(j & 1) * 2]);
            #pragma unroll
            for (int p = 0; p < 4; p++) {
                int rw = nbase + p * 16 + row_b;
                uint32_t c = (uint32_t)((2 * kc + qb_hi) ^ ((rw >> 1) & 3));
                ldm4(bf[p], base + 3 * ABUF + rw * RSB + c * 16);
            }
            #pragma unroll
            for (int i = 0; i < 2; i++)
                #pragma unroll
                for (int j = 0; j < 8; j++)
                    mma_bf16(acc[i][j], af[i], &bf[j >> 1][(j & 1) * 2]);
        }
    }
    __syncthreads();

    float* stage = (float*)dynsm;   // [128][130]
    #pragma unroll
    for (int i = 0; i < 2; i++) {
        #pragma unroll
        for (int j = 0; j < 8; j++) {
            int r = mbase + i * 16 + (lane >> 2);
            int c = nbase + j * 8 + (lane & 3) * 2;
            stage[r * 130 + c]           = acc[i][j][0];
            stage[r * 130 + c + 1]       = acc[i][j][1];
            stage[(r + 8) * 130 + c]     = acc[i][j][2];
            stage[(r + 8) * 130 + c + 1] = acc[i][j][3];
        }
    }
    __syncthreads();

    #pragma unroll
    for (int it = 0; it < 16; it++) {
        const int m = it * 8 + wid;
        const float bi = bias[m0 + m];
        float* crow = &C[(size_t)(m0 + m) * HW + n0];
        #pragma unroll
        for (int jj = 0; jj < 4; jj++) {
            int n = (tid & 31) + jj * 32;
            crow[n] = stage[m * 130 + n] + bi;
        }
    }
#undef ISSUE_SLAB
}

// ===========================================================================
// Window MHA v4 (tensor-core, round-14 compute).
// SHIFT=0 (branch 1): writes fp32 g_attnT.
// SHIFT=4 (branch 2): reads g_attnT, adds own result, splits to g_at_hi/lo
// (fuses the former sum_split kernel; every interior pixel is covered by
// exactly one clipped shifted window). Branch 2 launches AFTER branch 1.
// ===========================================================================
#define AT_STGQ 0
#define AT_STGK 16640
#define AT_STGV 33280
#define AT_QH   49664
#define AT_SMEM (49664 + 6 * 8192)   // 98816

template <int SHIFT, int NW>
static __device__ __forceinline__ void wattn_body(int widx, char* sm)
{
    const int tid  = threadIdx.x;
    const int lane = tid & 31;
    const int w    = tid >> 5;
    const int head = blockIdx.y;
    const int b    = blockIdx.z;
    const int wy = widx / NW, wx = widx % NW;
    const int y0 = wy * 8 - SHIFT, x0 = wx * 8 - SHIFT;

    const float* base = g_qkv + (size_t)b * C3 * HW;
    const int chq = head * HD;

    float* stgQ = (float*)(sm + AT_STGQ);   // [64][65]
    float* stgK = (float*)(sm + AT_STGK);   // [64][65]
    float* stgV = (float*)(sm + AT_STGV);   // [64][64]
    char* qh = sm + AT_QH;
    char* ql = qh + 8192;
    char* kh = qh + 16384;
    char* kl = qh + 24576;
    char* vh = qh + 32768;
    char* vl = qh + 40960;

    // ---- phase 1: fp32 load into staging ----
    #pragma unroll
    for (int it = 0; it < 16; it++) {
        int idx = tid + it * 256;        // idx = d*64 + n
        int d = idx >> 6, n = idx & 63;
        int y = y0 + (n >> 3), x = x0 + (n & 7);
        float qv = 0.f, kv = 0.f, vv = 0.f;
        if (SHIFT == 0 || ((unsigned)y < H_ && (unsigned)x < W_)) {
            size_t poff = (size_t)y * W_ + x;
            qv = base[(size_t)(chq + d) * HW + poff];
            kv = base[(size_t)(CQ + chq + d) * HW + poff];
            vv = base[(size_t)(2 * CQ + chq + d) * HW + poff];
        }
        stgQ[d * 65 + n] = qv;
        stgK[d * 65 + n] = kv;
        stgV[d * 64 + n] = vv;
    }
    __syncthreads();

    // ---- phase 2a: Q,K transpose-convert -> [n][d] bf16 hi/lo, swizzled ----
    #pragma unroll
    for (int a2 = 0; a2 < 2; a2++) {
        int id = a2 * 256 + tid;         // 0..511
        int n = id >> 3, c = id & 7;
        uint32_t dst = (uint32_t)(n * 128 + ((c ^ (n & 7)) * 16));
        float f[8];
        #pragma unroll
        for (int i = 0; i < 8; i++) f[i] = stgQ[(c * 8 + i) * 65 + n];
        uint4 hi, lo;
        split8(f, hi, lo);
        *(uint4*)(qh + dst) = hi;
        *(uint4*)(ql + dst) = lo;
        #pragma unroll
        for (int i = 0; i < 8; i++) f[i] = stgK[(c * 8 + i) * 65 + n];
        split8(f, hi, lo);
        *(uint4*)(kh + dst) = hi;
        *(uint4*)(kl + dst) = lo;
    }
    // ---- phase 2b: V convert -> [d][j] bf16 hi/lo, swizzled (no transpose) --
    #pragma unroll
    for (int v2 = 0; v2 < 2; v2++) {
        int id = v2 * 256 + tid;
        int d = id >> 3, c = id & 7;
        float f[8];
        *(float4*)&f[0] = *(const float4*)&stgV[d * 64 + c * 8];
        *(float4*)&f[4] = *(const float4*)&stgV[d * 64 + c * 8 + 4];
        uint4 hi, lo;
        split8(f, hi, lo);
        uint32_t dst = (uint32_t)(d * 128 + ((c ^ (d & 7)) * 16));
        *(uint4*)(vh + dst) = hi;
        *(uint4*)(vl + dst) = lo;
    }
    __syncthreads();

    // ---- per-warp tiles ----
    const int mt = w & 3;                // query 16-row tile
    const int dh = w >> 2;               // output d-half (0/1)
    const int row_a = (lane & 7) + ((lane >> 3) & 1) * 8;
    const int qa_hi = lane >> 4;
    const int row_b = (lane & 7) + (lane >> 4) * 8;
    const int qb_hi = (lane >> 3) & 1;

    const uint32_t qh_a = smem_u32(qh);
    const uint32_t kh_a = smem_u32(kh);
    const uint32_t vh_a = smem_u32(vh);

    // ---- phase 3: S = Q K^T (bf16x3) ----
    float acc[8][4];
    #pragma unroll
    for (int j = 0; j < 8; j++)
        #pragma unroll
        for (int r = 0; r < 4; r++) acc[j][r] = 0.f;

    #pragma unroll
    for (int kc = 0; kc < 4; kc++) {
        uint32_t aq[4], aql[4], bh[4][4], bl[4][4];
        {
            int rw = mt * 16 + row_a;
            uint32_t cc = (uint32_t)((2 * kc + qa_hi) ^ (rw & 7));
            uint32_t ra = qh_a + rw * 128 + cc * 16;
            ldm4(aq, ra);
            ldm4(aql, ra + 8192);
        }
        #pragma unroll
        for (int p = 0; p < 4; p++) {
            int rw = p * 16 + row_b;
            uint32_t cc = (uint32_t)((2 * kc + qb_hi) ^ (rw & 7));
            uint32_t rb = kh_a + rw * 128 + cc * 16;
            ldm4(bh[p], rb);
            ldm4(bl[p], rb + 8192);
        }
        #pragma unroll
        for (int j = 0; j < 8; j++)
            mma_bf16(acc[j], aq, &bh[j >> 1][(j & 1) * 2]);
        #pragma unroll
        for (int j = 0; j < 8; j++)
            mma_bf16(acc[j], aql, &bh[j >> 1][(j & 1) * 2]);
        #pragma unroll
        for (int j = 0; j < 8; j++)
            mma_bf16(acc[j], aq, &bl[j >> 1][(j & 1) * 2]);
    }

    // ---- phase 4: softmax (warp-local; rows r=lane>>2 and r+8) ----
    const float scale = 0.125f;
    float mx0 = acc[0][0], mx1 = acc[0][2];
    #pragma unroll
    for (int j = 0; j < 8; j++) {
        mx0 = fmaxf(mx0, fmaxf(acc[j][0], acc[j][1]));
        mx1 = fmaxf(mx1, fmaxf(acc[j][2], acc[j][3]));
    }
    mx0 = fmaxf(mx0, __shfl_xor_sync(0xffffffffu, mx0, 1));
    mx0 = fmaxf(mx0, __shfl_xor_sync(0xffffffffu, mx0, 2));
    mx1 = fmaxf(mx1, __shfl_xor_sync(0xffffffffu, mx1, 1));
    mx1 = fmaxf(mx1, __shfl_xor_sync(0xffffffffu, mx1, 2));
    float sum0 = 0.f, sum1 = 0.f;
    #pragma unroll
    for (int j = 0; j < 8; j++) {
        acc[j][0] = __expf((acc[j][0] - mx0) * scale); sum0 += acc[j][0];
        acc[j][1] = __expf((acc[j][1] - mx0) * scale); sum0 += acc[j][1];
        acc[j][2] = __expf((acc[j][2] - mx1) * scale); sum1 += acc[j][2];
        acc[j][3] = __expf((acc[j][3] - mx1) * scale); sum1 += acc[j][3];
    }
    sum0 += __shfl_xor_sync(0xffffffffu, sum0, 1);
    sum0 += __shfl_xor_sync(0xffffffffu, sum0, 2);
    sum1 += __shfl_xor_sync(0xffffffffu, sum1, 1);
    sum1 += __shfl_xor_sync(0xffffffffu, sum1, 2);
    const float inv0 = 1.f / sum0, inv1 = 1.f / sum1;

    // ---- repack P into A-frags (hi/lo) ----
    uint32_t aph[4][4], apl[4][4];
    #pragma unroll
    for (int kc = 0; kc < 4; kc++) {
        const int j0 = 2 * kc, j1 = 2 * kc + 1;
        float p00 = acc[j0][0] * inv0, p01 = acc[j0][1] * inv0;
        float p02 = acc[j0][2] * inv1, p03 = acc[j0][3] * inv1;
        float p10 = acc[j1][0] * inv0, p11 = acc[j1][1] * inv0;
        float p12 = acc[j1][2] * inv1, p13 = acc[j1][3] * inv1;
        uint32_t h;
        h = pack_bf16x2(p00, p01); aph[kc][0] = h;
        apl[kc][0] = pack_bf16x2(p00 - bf16lo_f(h), p01 - bf16hi_f(h));
        h = pack_bf16x2(p02, p03); aph[kc][1] = h;
        apl[kc][1] = pack_bf16x2(p02 - bf16lo_f(h), p03 - bf16hi_f(h));
        h = pack_bf16x2(p10, p11); aph[kc][2] = h;
        apl[kc][2] = pack_bf16x2(p10 - bf16lo_f(h), p11 - bf16hi_f(h));
        h = pack_bf16x2(p12, p13); aph[kc][3] = h;
        apl[kc][3] = pack_bf16x2(p12 - bf16lo_f(h), p13 - bf16hi_f(h));
    }

    // ---- phase 5: O = P V (bf16x3), d-half per warp ----
    float oacc[4][4];
    #pragma unroll
    for (int t = 0; t < 4; t++)
        #pragma unroll
        for (int r = 0; r < 4; r++) oacc[t][r] = 0.f;

    #pragma unroll
    for (int kc = 0; kc < 4; kc++) {
        uint32_t bvh[2][4], bvl[2][4];
        #pragma unroll
        for (int p = 0; p < 2; p++) {
            int rw = dh * 32 + p * 16 + row_b;
            uint32_t cc = (uint32_t)((2 * kc + qb_hi) ^ (rw & 7));
            uint32_t rb = vh_a + rw * 128 + cc * 16;
            ldm4(bvh[p], rb);
            ldm4(bvl[p], rb + 8192);
        }
        #pragma unroll
        for (int t = 0; t < 4; t++)
            mma_bf16(oacc[t], aph[kc], &bvh[t >> 1][(t & 1) * 2]);
        #pragma unroll
        for (int t = 0; t < 4; t++)
            mma_bf16(oacc[t], apl[kc], &bvh[t >> 1][(t & 1) * 2]);
        #pragma unroll
        for (int t = 0; t < 4; t++)
            mma_bf16(oacc[t], aph[kc], &bvl[t >> 1][(t & 1) * 2]);
    }

    // ---- phase 6: store O ----
    const int ntok0 = mt * 16 + (lane >> 2);
    const int cb = chq + dh * 32 + (lane & 3) * 2;
    #pragma unroll
    for (int half = 0; half < 2; half++) {
        int n = ntok0 + half * 8;
        int y = y0 + (n >> 3), x = x0 + (n & 7);
        if (SHIFT == 0 || ((unsigned)y < H_ && (unsigned)x < W_)) {
            size_t pix = ((size_t)b * HW + (size_t)y * W_ + x) * CQ;
            if (SHIFT == 0) {
                float* op = g_attnT + pix;
                #pragma unroll
                for (int t = 0; t < 4; t++) {
                    float2 v;
                    v.x = oacc[t][half * 2 + 0];
                    v.y = oacc[t][half * 2 + 1];
                    *(float2*)&op[cb + t * 8] = v;
                }
            } else {
                // fused: add branch-1 result, split to bf16 hi/lo
                const float* a1 = g_attnT + pix;
                #pragma unroll
                for (int t = 0; t < 4; t++) {
                    float2 v = *(const float2*)&a1[cb + t * 8];
                    float f0 = v.x + oacc[t][half * 2 + 0];
                    float f1 = v.y + oacc[t][half * 2 + 1];
                    uint32_t h = pack_bf16x2(f0, f1);
                    uint32_t l = pack_bf16x2(f0 - bf16lo_f(h), f1 - bf16hi_f(h));
                    *(uint32_t*)&g_at_hi[pix + cb + t * 8] = h;
                    *(uint32_t*)&g_at_lo[pix + cb + t * 8] = l;
                }
            }
        }
    }
}

__global__ __launch_bounds__(256) void wattn1_kernel()
{
    extern __shared__ char dynat[];
    wattn_body<0, 16>(blockIdx.x, dynat);
}

__global__ __launch_bounds__(256) void wattn2_kernel()
{
    extern __shared__ char dynat[];
    wattn_body<4, 17>(blockIdx.x, dynat);
}

// ---------------------------------------------------------------------------
extern "C" void kernel_launch(void* const* d_in, const int* in_sizes, int n_in,
                              void* d_out, int out_size)
{
    (void)in_sizes; (void)n_in; (void)out_size;
    const float* x      = (const float*)d_in[0];
    const float* w_qkv  = (const float*)d_in[1];
    const float* b_qkv  = (const float*)d_in[2];
    const float* w_head = (const float*)d_in[3];
    const float* b_head = (const float*)d_in[4];
    float* out = (float*)d_out;

    cudaFuncSetAttribute(gemm_bf16x3_kernel,
                         cudaFuncAttributeMaxDynamicSharedMemorySize, GEMM_SMEM);
    cudaFuncSetAttribute(wattn1_kernel,
                         cudaFuncAttributeMaxDynamicSharedMemorySize, AT_SMEM);
    cudaFuncSetAttribute(wattn2_kernel,
                         cudaFuncAttributeMaxDynamicSharedMemorySize, AT_SMEM);

    // 0a) split weights (device-side symbol selection)
    prep_w_kernel<<<(C3 * KDIM / 4 + 255) / 256, 256>>>(w_qkv, 0, C3 * KDIM / 4);
    prep_w_kernel<<<(CQ * KDIM / 4 + 255) / 256, 256>>>(w_head, 1, CQ * KDIM / 4);
    // 0b) transpose + split x -> g_xb_hi/lo [b][hw][c]
    {
        dim3 grid(HW / 32, CIN / 32, NB);
        transpose_x_kernel<<<grid, 256>>>(x);
    }
    // 1) qkv = w_qkv @ x + b_qkv  (M=1152)
    {
        dim3 grid(C3 / 128, HW / 128, NB);
        gemm_bf16x3_kernel<<<grid, 256, GEMM_SMEM>>>(b_qkv, nullptr, 0);
    }
    // 2) branch 1: aligned windows -> g_attnT (fp32)
    {
        dim3 grid(256, NH, NB);
        wattn1_kernel<<<grid, 256, AT_SMEM>>>();
    }
    // 3) branch 2: shifted windows; fused add + split -> g_at_hi/lo
    {
        dim3 grid(289, NH, NB);
        wattn2_kernel<<<grid, 256, AT_SMEM>>>();
    }
    // 4) out = w_head @ (x1+x2) + b_head  (M=384)
    {
        dim3 grid(CQ / 128, HW / 128, NB);
        gemm_bf16x3_kernel<<<grid, 256, GEMM_SMEM>>>(b_head, out, 1);
    }
}

// round 16
// speedup vs baseline: 1.1404x; 1.1404x over previous
#include <cuda_runtime.h>
#include <cstdint>

#define H_ 128
#define W_ 128
#define HW 16384
#define CIN 384
#define CQ 384
#define C3 1152
#define NH 6
#define HD 64
#define NB 4
#define KDIM 384          // K for both GEMMs
#define NSLAB 12          // 384 / 32

// Scratch (no allocation allowed). RULE: device globals are referenced ONLY
// from device code — never passed as kernel args from host (ATS makes the
// host shadow symbol silently writable -> zero-filled device arrays).
__device__ uint16_t g_qk_hi [(size_t)NB * HW * 768];  // q|k bf16 hi, token-major
__device__ uint16_t g_qk_lo [(size_t)NB * HW * 768];  // q|k bf16 lo
__device__ float    g_v     [(size_t)NB * HW * 384];  // v fp32, token-major
__device__ float    g_attnT [(size_t)NB * HW * CQ];   // branch-1 out (fp32)
__device__ float    g_attnT2[(size_t)NB * HW * CQ];   // branch-2 out (fp32)
__device__ uint16_t g_xb_hi [(size_t)NB * HW * CIN];  // x^T bf16 hi [b][hw][c]
__device__ uint16_t g_xb_lo [(size_t)NB * HW * CIN];
__device__ uint16_t g_at_hi [(size_t)NB * HW * CQ];   // (attn1+attn2) bf16 hi
__device__ uint16_t g_at_lo [(size_t)NB * HW * CQ];
__device__ uint16_t g_wq_hi [C3 * KDIM];
__device__ uint16_t g_wq_lo [C3 * KDIM];
__device__ uint16_t g_wh_hi [CQ * KDIM];
__device__ uint16_t g_wh_lo [CQ * KDIM];

// ===========================================================================
// helpers (baseline PTX, valid in every sm_103 gencode pass)
// ===========================================================================
static __device__ __forceinline__ void mma_bf16(
    float* d, const uint32_t* a, const uint32_t* b)
{
    asm volatile(
        "mma.sync.aligned.m16n8k16.row.col.f32.bf16.bf16.f32 "
        "{%0,%1,%2,%3}, {%4,%5,%6,%7}, {%8,%9}, {%0,%1,%2,%3};"
        : "+f"(d[0]), "+f"(d[1]), "+f"(d[2]), "+f"(d[3])
        : "r"(a[0]), "r"(a[1]), "r"(a[2]), "r"(a[3]),
          "r"(b[0]), "r"(b[1]));
}

static __device__ __forceinline__ void ldm4(uint32_t* r, uint32_t addr)
{
    asm volatile(
        "ldmatrix.sync.aligned.m8n8.x4.shared.b16 {%0,%1,%2,%3}, [%4];"
        : "=r"(r[0]), "=r"(r[1]), "=r"(r[2]), "=r"(r[3])
        : "r"(addr));
}

static __device__ __forceinline__ uint32_t smem_u32(const void* p) {
    uint32_t a;
    asm("{ .reg .u64 t; cvta.to.shared.u64 t, %1; cvt.u32.u64 %0, t; }"
        : "=r"(a) : "l"(p));
    return a;
}

static __device__ __forceinline__ uint32_t pack_bf16x2(float lo, float hi) {
    uint32_t r;
    asm("cvt.rn.bf16x2.f32 %0, %1, %2;" : "=r"(r) : "f"(hi), "f"(lo));
    return r;
}
static __device__ __forceinline__ float bf16lo_f(uint32_t r) {
    return __uint_as_float(r << 16);
}
static __device__ __forceinline__ float bf16hi_f(uint32_t r) {
    return __uint_as_float(r & 0xFFFF0000u);
}

// split 8 consecutive floats into bf16 hi/lo uint4s
static __device__ __forceinline__ void split8(const float* f, uint4& hi, uint4& lo)
{
    hi.x = pack_bf16x2(f[0], f[1]);
    hi.y = pack_bf16x2(f[2], f[3]);
    hi.z = pack_bf16x2(f[4], f[5]);
    hi.w = pack_bf16x2(f[6], f[7]);
    lo.x = pack_bf16x2(f[0] - bf16lo_f(hi.x), f[1] - bf16hi_f(hi.x));
    lo.y = pack_bf16x2(f[2] - bf16lo_f(hi.y), f[3] - bf16hi_f(hi.y));
    lo.z = pack_bf16x2(f[4] - bf16lo_f(hi.z), f[5] - bf16hi_f(hi.z));
    lo.w = pack_bf16x2(f[6] - bf16lo_f(hi.w), f[7] - bf16hi_f(hi.w));
}

#define CP_ASYNC16(sa, gp) \
    asm volatile("cp.async.cg.shared.global [%0], [%1], 16;" :: "r"(sa), "l"(gp))
#define CP_COMMIT() asm volatile("cp.async.commit_group;" ::: "memory")
#define CP_WAIT(n)  asm volatile("cp.async.wait_group %0;" :: "n"(n) : "memory")

// ===========================================================================
// prep: split weights into bf16 hi/lo (device-side target selection)
// ===========================================================================
__global__ __launch_bounds__(256) void prep_w_kernel(
    const float* __restrict__ w, int which, int n4)
{
    uint16_t* hi = which ? g_wh_hi : g_wq_hi;
    uint16_t* lo = which ? g_wh_lo : g_wq_lo;
    int i = blockIdx.x * 256 + threadIdx.x;
    if (i >= n4) return;
    float4 v = ((const float4*)w)[i];
    uint2 h, l;
    h.x = pack_bf16x2(v.x, v.y);
    h.y = pack_bf16x2(v.z, v.w);
    l.x = pack_bf16x2(v.x - bf16lo_f(h.x), v.y - bf16hi_f(h.x));
    l.y = pack_bf16x2(v.z - bf16lo_f(h.y), v.w - bf16hi_f(h.y));
    ((uint2*)hi)[i] = h;
    ((uint2*)lo)[i] = l;
}

// ===========================================================================
// Transpose + split: x[b][C][HW] -> g_xb_hi/lo [b][hw][c]
// ===========================================================================
__global__ __launch_bounds__(256) void transpose_x_kernel(const float* __restrict__ x)
{
    __shared__ float sm[32][33];
    const int z = blockIdx.z;
    const int hw0 = blockIdx.x * 32, c0 = blockIdx.y * 32;
    const float* xz = x + (size_t)z * CIN * HW;
    uint16_t* th = g_xb_hi + (size_t)z * HW * CIN;
    uint16_t* tl = g_xb_lo + (size_t)z * HW * CIN;
    const int t = threadIdx.x;
    const int tx = t & 31, ty = t >> 5;

    #pragma unroll
    for (int i = 0; i < 4; i++)
        sm[ty + 8 * i][tx] = xz[(size_t)(c0 + ty + 8 * i) * HW + hw0 + tx];
    __syncthreads();

    {
        int h = t >> 3, cp = (t & 7) * 4;
        float v0 = sm[cp + 0][h], v1 = sm[cp + 1][h];
        float v2 = sm[cp + 2][h], v3 = sm[cp + 3][h];
        uint2 hi, lo;
        hi.x = pack_bf16x2(v0, v1);
        hi.y = pack_bf16x2(v2, v3);
        lo.x = pack_bf16x2(v0 - bf16lo_f(hi.x), v1 - bf16hi_f(hi.x));
        lo.y = pack_bf16x2(v2 - bf16lo_f(hi.y), v3 - bf16hi_f(hi.y));
        size_t off = (size_t)(hw0 + h) * CIN + c0 + cp;
        *(uint2*)&th[off] = hi;
        *(uint2*)&tl[off] = lo;
    }
}

// ===========================================================================
// sum + split: g_at_hi/lo = split(g_attnT + g_attnT2)
// ===========================================================================
__global__ __launch_bounds__(256) void sum_split_kernel()
{
    int i = blockIdx.x * 256 + threadIdx.x;   // float4 index
    float4 a = ((const float4*)g_attnT)[i];
    float4 b = ((const float4*)g_attnT2)[i];
    float v0 = a.x + b.x, v1 = a.y + b.y, v2 = a.z + b.z, v3 = a.w + b.w;
    uint2 h, l;
    h.x = pack_bf16x2(v0, v1);
    h.y = pack_bf16x2(v2, v3);
    l.x = pack_bf16x2(v0 - bf16lo_f(h.x), v1 - bf16hi_f(h.x));
    l.y = pack_bf16x2(v2 - bf16lo_f(h.y), v3 - bf16hi_f(h.y));
    ((uint2*)g_at_hi)[i] = h;
    ((uint2*)g_at_lo)[i] = l;
}

// ===========================================================================
// bf16x3-split tensor-core GEMM (round-13 mainloop).
// mode 0: A = g_wq, B = g_xb. Epilogue writes TOKEN-MAJOR:
//         m0 < 768  -> g_qk_hi/lo[b][hw][768] (bf16 split, bias added)
//         m0 >= 768 -> g_v[b][hw][384] (fp32, bias added)
// mode 1: A = g_wh, B = g_at. Epilogue writes channel-major fp32 out.
// ===========================================================================
#define RSB   64
#define ABUF  8192
#define SMBUF 32768
#define NSTG  3
#define GEMM_SMEM (NSTG * SMBUF)

__global__ __launch_bounds__(256, 2) void gemm_bf16x3_kernel(
    const float* __restrict__ bias, float* __restrict__ Cext, int mode)
{
    extern __shared__ char dynsm[];
    const uint32_t sbase = smem_u32(dynsm);

    const int tid  = threadIdx.x;
    const int lane = tid & 31;
    const int wid  = tid >> 5;
    const int m0 = blockIdx.x * 128;
    const int n0 = blockIdx.y * 128;
    const int z  = blockIdx.z;

    const uint16_t* Ahi = (mode == 0) ? g_wq_hi : g_wh_hi;
    const uint16_t* Alo = (mode == 0) ? g_wq_lo : g_wh_lo;
    const uint16_t* Bhi = ((mode == 0) ? g_xb_hi : g_at_hi) + (size_t)z * HW * KDIM;
    const uint16_t* Blo = ((mode == 0) ? g_xb_lo : g_at_lo) + (size_t)z * HW * KDIM;

    const uint16_t* gptr[8];
    uint32_t soff[8];
    #pragma unroll
    for (int i = 0; i < 8; i++) {
        int id  = i * 256 + tid;
        int arr = id >> 9;
        int idx = id & 511;
        int r   = idx >> 2;
        int q   = idx & 3;
        const uint16_t* base =
            (arr == 0) ? Ahi + (size_t)(m0 + r) * KDIM :
            (arr == 1) ? Alo + (size_t)(m0 + r) * KDIM :
            (arr == 2) ? Bhi + (size_t)(n0 + r) * KDIM :
                         Blo + (size_t)(n0 + r) * KDIM;
        gptr[i] = base + q * 8;
        soff[i] = (uint32_t)(arr * ABUF + r * RSB + ((q ^ ((r >> 1) & 3)) * 16));
    }

#define ISSUE_SLAB(k0, bufOff) do {                                           \
        _Pragma("unroll")                                                     \
        for (int i = 0; i < 8; i++)                                           \
            CP_ASYNC16(sbase + (bufOff) + soff[i], gptr[i] + (k0));           \
        CP_COMMIT();                                                          \
    } while (0)

    const int mbase = (wid & 3) * 32;
    const int nbase = (wid >> 2) * 64;
    const int row_a = (lane & 7) + ((lane >> 3) & 1) * 8;
    const int qa_hi = lane >> 4;
    const int row_b = (lane & 7) + (lane >> 4) * 8;
    const int qb_hi = (lane >> 3) & 1;

    float acc[2][8][4];
    #pragma unroll
    for (int i = 0; i < 2; i++)
        #pragma unroll
        for (int j = 0; j < 8; j++)
            #pragma unroll
            for (int r = 0; r < 4; r++) acc[i][j][r] = 0.f;

    ISSUE_SLAB(0, 0);
    ISSUE_SLAB(32, SMBUF);

    for (int s = 0; s < NSLAB; s++) {
        if (s + 1 < NSLAB) CP_WAIT(1);
        else               CP_WAIT(0);
        __syncthreads();
        if (s + 2 < NSLAB) ISSUE_SLAB((s + 2) * 32, ((s + 2) % NSTG) * SMBUF);

        const uint32_t base = sbase + (s % NSTG) * SMBUF;
        #pragma unroll
        for (int kc = 0; kc < 2; kc++) {
            uint32_t af[2][4], al[2][4], bf[4][4];
            #pragma unroll
            for (int i = 0; i < 2; i++) {
                int rw = mbase + i * 16 + row_a;
                uint32_t c = (uint32_t)((2 * kc + qa_hi) ^ ((rw >> 1) & 3));
                uint32_t ra_ = base + rw * RSB + c * 16;
                ldm4(af[i], ra_);
                ldm4(al[i], ra_ + ABUF);
            }
            #pragma unroll
            for (int p = 0; p < 4; p++) {
                int rw = nbase + p * 16 + row_b;
                uint32_t c = (uint32_t)((2 * kc + qb_hi) ^ ((rw >> 1) & 3));
                ldm4(bf[p], base + 2 * ABUF + rw * RSB + c * 16);
            }
            #pragma unroll
            for (int i = 0; i < 2; i++)
                #pragma unroll
                for (int j = 0; j < 8; j++)
                    mma_bf16(acc[i][j], af[i], &bf[j >> 1][(j & 1) * 2]);
            #pragma unroll
            for (int i = 0; i < 2; i++)
                #pragma unroll
                for (int j = 0; j < 8; j++)
                    mma_bf16(acc[i][j], al[i], &bf[j >> 1][(j & 1) * 2]);
            #pragma unroll
            for (int p = 0; p < 4; p++) {
                int rw = nbase + p * 16 + row_b;
                uint32_t c = (uint32_t)((2 * kc + qb_hi) ^ ((rw >> 1) & 3));
                ldm4(bf[p], base + 3 * ABUF + rw * RSB + c * 16);
            }
            #pragma unroll
            for (int i = 0; i < 2; i++)
                #pragma unroll
                for (int j = 0; j < 8; j++)
                    mma_bf16(acc[i][j], af[i], &bf[j >> 1][(j & 1) * 2]);
        }
    }
    __syncthreads();

    if (mode == 0) {
        // transposed stage [n 128][m 132]
        float* stage = (float*)dynsm;
        #pragma unroll
        for (int i = 0; i < 2; i++) {
            #pragma unroll
            for (int j = 0; j < 8; j++) {
                int r = mbase + i * 16 + (lane >> 2);
                int c = nbase + j * 8 + (lane & 3) * 2;
                stage[c * 132 + r]           = acc[i][j][0];
                stage[(c + 1) * 132 + r]     = acc[i][j][1];
                stage[c * 132 + r + 8]       = acc[i][j][2];
                stage[(c + 1) * 132 + r + 8] = acc[i][j][3];
            }
        }
        __syncthreads();

        const int m4 = (tid & 31) * 4;
        float4 bi4 = *(const float4*)&bias[m0 + m4];
        const bool isv = (m0 >= 768);
        #pragma unroll
        for (int it = 0; it < 16; it++) {
            const int n = it * 8 + wid;
            float4 f = *(float4*)&stage[n * 132 + m4];
            f.x += bi4.x; f.y += bi4.y; f.z += bi4.z; f.w += bi4.w;
            size_t pix = (size_t)z * HW + n0 + n;
            if (!isv) {
                uint2 h, l;
                h.x = pack_bf16x2(f.x, f.y);
                h.y = pack_bf16x2(f.z, f.w);
                l.x = pack_bf16x2(f.x - bf16lo_f(h.x), f.y - bf16hi_f(h.x));
                l.y = pack_bf16x2(f.z - bf16lo_f(h.y), f.w - bf16hi_f(h.y));
                *(uint2*)&g_qk_hi[pix * 768 + m0 + m4] = h;
                *(uint2*)&g_qk_lo[pix * 768 + m0 + m4] = l;
            } else {
                *(float4*)&g_v[pix * 384 + (m0 - 768) + m4] = f;
            }
        }
    } else {
        float* C = Cext + (size_t)z * CQ * HW;
        float* stage = (float*)dynsm;   // [128 m][130 n]
        #pragma unroll
        for (int i = 0; i < 2; i++) {
            #pragma unroll
            for (int j = 0; j < 8; j++) {
                int r = mbase + i * 16 + (lane >> 2);
                int c = nbase + j * 8 + (lane & 3) * 2;
                stage[r * 130 + c]           = acc[i][j][0];
                stage[r * 130 + c + 1]       = acc[i][j][1];
                stage[(r + 8) * 130 + c]     = acc[i][j][2];
                stage[(r + 8) * 130 + c + 1] = acc[i][j][3];
            }
        }
        __syncthreads();

        #pragma unroll
        for (int it = 0; it < 16; it++) {
            const int m = it * 8 + wid;
            const float bi = bias[m0 + m];
            float* crow = &C[(size_t)(m0 + m) * HW + n0];
            #pragma unroll
            for (int jj = 0; jj < 4; jj++) {
                int n = (tid & 31) + jj * 32;
                crow[n] = stage[m * 130 + n] + bi;
            }
        }
    }
#undef ISSUE_SLAB
}

// ===========================================================================
// Window MHA v5: tensor-core; Q/K loaded DIRECTLY as pre-split bf16 from
// g_qk_hi/lo (token-major), V staged fp32 from g_v then transpose-converted.
// smem: stgV [64][68] fp32 (17408B) + 6 bf16 arrays [64][64] swizzled
// (chunk c at c ^ (row&7)). Total 66560B -> 3 CTAs/SM.
// Merged launch: blockIdx.x < 256 -> branch 1 (g_attnT), else branch 2
// (g_attnT2). sum_split combines afterwards.
// ===========================================================================
#define AT_QH   17408
#define AT_SMEM (17408 + 6 * 8192)   // 66560

template <int SHIFT, int NW>
static __device__ __forceinline__ void wattn_body(int widx, char* sm)
{
    const int tid  = threadIdx.x;
    const int lane = tid & 31;
    const int w    = tid >> 5;
    const int head = blockIdx.y;
    const int b    = blockIdx.z;
    const int wy = widx / NW, wx = widx % NW;
    const int y0 = wy * 8 - SHIFT, x0 = wx * 8 - SHIFT;

    const int chq = head * HD;
    const uint16_t* qksrc_h = g_qk_hi + (size_t)b * HW * 768;
    const uint16_t* qksrc_l = g_qk_lo + (size_t)b * HW * 768;
    const float*    vsrc    = g_v     + (size_t)b * HW * 384;

    float* stgV = (float*)sm;            // [64][68]
    char* qh = sm + AT_QH;
    char* ql = qh + 8192;
    char* kh = qh + 16384;
    char* kl = qh + 24576;
    char* vh = qh + 32768;
    char* vl = qh + 40960;

    // ---- phase 1a: Q/K direct bf16 loads -> swizzled smem ----
    #pragma unroll
    for (int it = 0; it < 8; it++) {
        int id  = it * 256 + tid;         // 0..2047
        int arr = id >> 9;                // 0 qh, 1 ql, 2 kh, 3 kl
        int n   = (id >> 3) & 63;
        int c   = id & 7;
        int y = y0 + (n >> 3), x = x0 + (n & 7);
        uint4 v = make_uint4(0u, 0u, 0u, 0u);
        if (SHIFT == 0 || ((unsigned)y < H_ && (unsigned)x < W_)) {
            const uint16_t* src = (arr & 1) ? qksrc_l : qksrc_h;
            int coff = ((arr >> 1) ? 384 : 0) + chq + c * 8;
            v = *(const uint4*)&src[((size_t)y * W_ + x) * 768 + coff];
        }
        char* dstArr = (arr == 0) ? qh : (arr == 1) ? ql : (arr == 2) ? kh : kl;
        *(uint4*)(dstArr + n * 128 + ((c ^ (n & 7)) * 16)) = v;
    }

    // ---- phase 1b: V fp32 stage (token-major src -> transposed [d][j]) ----
    #pragma unroll
    for (int it = 0; it < 4; it++) {
        int id = it * 256 + tid;          // 0..1023
        int j  = id >> 4;                 // token
        int d4 = (id & 15) * 4;
        int y = y0 + (j >> 3), x = x0 + (j & 7);
        float4 f = make_float4(0.f, 0.f, 0.f, 0.f);
        if (SHIFT == 0 || ((unsigned)y < H_ && (unsigned)x < W_))
            f = *(const float4*)&vsrc[((size_t)y * W_ + x) * 384 + chq + d4];
        stgV[(d4 + 0) * 68 + j] = f.x;
        stgV[(d4 + 1) * 68 + j] = f.y;
        stgV[(d4 + 2) * 68 + j] = f.z;
        stgV[(d4 + 3) * 68 + j] = f.w;
    }
    __syncthreads();

    // ---- phase 2: V convert -> [d][j] bf16 hi/lo, swizzled ----
    #pragma unroll
    for (int v2 = 0; v2 < 2; v2++) {
        int id = v2 * 256 + tid;
        int d = id >> 3, c = id & 7;
        float f[8];
        *(float4*)&f[0] = *(const float4*)&stgV[d * 68 + c * 8];
        *(float4*)&f[4] = *(const float4*)&stgV[d * 68 + c * 8 + 4];
        uint4 hi, lo;
        split8(f, hi, lo);
        uint32_t dst = (uint32_t)(d * 128 + ((c ^ (d & 7)) * 16));
        *(uint4*)(vh + dst) = hi;
        *(uint4*)(vl + dst) = lo;
    }
    __syncthreads();

    // ---- per-warp tiles ----
    const int mt = w & 3;                // query 16-row tile
    const int dh = w >> 2;               // output d-half (0/1)
    const int row_a = (lane & 7) + ((lane >> 3) & 1) * 8;
    const int qa_hi = lane >> 4;
    const int row_b = (lane & 7) + (lane >> 4) * 8;
    const int qb_hi = (lane >> 3) & 1;

    const uint32_t qh_a = smem_u32(qh);
    const uint32_t kh_a = smem_u32(kh);
    const uint32_t vh_a = smem_u32(vh);

    // ---- phase 3: S = Q K^T (bf16x3) ----
    float acc[8][4];
    #pragma unroll
    for (int j = 0; j < 8; j++)
        #pragma unroll
        for (int r = 0; r < 4; r++) acc[j][r] = 0.f;

    #pragma unroll
    for (int kc = 0; kc < 4; kc++) {
        uint32_t aq[4], aql[4], bh[4][4], bl[4][4];
        {
            int rw = mt * 16 + row_a;
            uint32_t cc = (uint32_t)((2 * kc + qa_hi) ^ (rw & 7));
            uint32_t ra = qh_a + rw * 128 + cc * 16;
            ldm4(aq, ra);
            ldm4(aql, ra + 8192);
        }
        #pragma unroll
        for (int p = 0; p < 4; p++) {
            int rw = p * 16 + row_b;
            uint32_t cc = (uint32_t)((2 * kc + qb_hi) ^ (rw & 7));
            uint32_t rb = kh_a + rw * 128 + cc * 16;
            ldm4(bh[p], rb);
            ldm4(bl[p], rb + 8192);
        }
        #pragma unroll
        for (int j = 0; j < 8; j++)
            mma_bf16(acc[j], aq, &bh[j >> 1][(j & 1) * 2]);
        #pragma unroll
        for (int j = 0; j < 8; j++)
            mma_bf16(acc[j], aql, &bh[j >> 1][(j & 1) * 2]);
        #pragma unroll
        for (int j = 0; j < 8; j++)
            mma_bf16(acc[j], aq, &bl[j >> 1][(j & 1) * 2]);
    }

    // ---- phase 4: softmax (warp-local; rows r=lane>>2 and r+8) ----
    const float scale = 0.125f;
    float mx0 = acc[0][0], mx1 = acc[0][2];
    #pragma unroll
    for (int j = 0; j < 8; j++) {
        mx0 = fmaxf(mx0, fmaxf(acc[j][0], acc[j][1]));
        mx1 = fmaxf(mx1, fmaxf(acc[j][2], acc[j][3]));
    }
    mx0 = fmaxf(mx0, __shfl_xor_sync(0xffffffffu, mx0, 1));
    mx0 = fmaxf(mx0, __shfl_xor_sync(0xffffffffu, mx0, 2));
    mx1 = fmaxf(mx1, __shfl_xor_sync(0xffffffffu, mx1, 1));
    mx1 = fmaxf(mx1, __shfl_xor_sync(0xffffffffu, mx1, 2));
    float sum0 = 0.f, sum1 = 0.f;
    #pragma unroll
    for (int j = 0; j < 8; j++) {
        acc[j][0] = __expf((acc[j][0] - mx0) * scale); sum0 += acc[j][0];
        acc[j][1] = __expf((acc[j][1] - mx0) * scale); sum0 += acc[j][1];
        acc[j][2] = __expf((acc[j][2] - mx1) * scale); sum1 += acc[j][2];
        acc[j][3] = __expf((acc[j][3] - mx1) * scale); sum1 += acc[j][3];
    }
    sum0 += __shfl_xor_sync(0xffffffffu, sum0, 1);
    sum0 += __shfl_xor_sync(0xffffffffu, sum0, 2);
    sum1 += __shfl_xor_sync(0xffffffffu, sum1, 1);
    sum1 += __shfl_xor_sync(0xffffffffu, sum1, 2);
    const float inv0 = 1.f / sum0, inv1 = 1.f / sum1;

    // ---- repack P into A-frags (hi/lo) ----
    uint32_t aph[4][4], apl[4][4];
    #pragma unroll
    for (int kc = 0; kc < 4; kc++) {
        const int j0 = 2 * kc, j1 = 2 * kc + 1;
        float p00 = acc[j0][0] * inv0, p01 = acc[j0][1] * inv0;
        float p02 = acc[j0][2] * inv1, p03 = acc[j0][3] * inv1;
        float p10 = acc[j1][0] * inv0, p11 = acc[j1][1] * inv0;
        float p12 = acc[j1][2] * inv1, p13 = acc[j1][3] * inv1;
        uint32_t h;
        h = pack_bf16x2(p00, p01); aph[kc][0] = h;
        apl[kc][0] = pack_bf16x2(p00 - bf16lo_f(h), p01 - bf16hi_f(h));
        h = pack_bf16x2(p02, p03); aph[kc][1] = h;
        apl[kc][1] = pack_bf16x2(p02 - bf16lo_f(h), p03 - bf16hi_f(h));
        h = pack_bf16x2(p10, p11); aph[kc][2] = h;
        apl[kc][2] = pack_bf16x2(p10 - bf16lo_f(h), p11 - bf16hi_f(h));
        h = pack_bf16x2(p12, p13); aph[kc][3] = h;
        apl[kc][3] = pack_bf16x2(p12 - bf16lo_f(h), p13 - bf16hi_f(h));
    }

    // ---- phase 5: O = P V (bf16x3), d-half per warp ----
    float oacc[4][4];
    #pragma unroll
    for (int t = 0; t < 4; t++)
        #pragma unroll
        for (int r = 0; r < 4; r++) oacc[t][r] = 0.f;

    #pragma unroll
    for (int kc = 0; kc < 4; kc++) {
        uint32_t bvh[2][4], bvl[2][4];
        #pragma unroll
        for (int p = 0; p < 2; p++) {
            int rw = dh * 32 + p * 16 + row_b;
            uint32_t cc = (uint32_t)((2 * kc + qb_hi) ^ (rw & 7));
            uint32_t rb = vh_a + rw * 128 + cc * 16;
            ldm4(bvh[p], rb);
            ldm4(bvl[p], rb + 8192);
        }
        #pragma unroll
        for (int t = 0; t < 4; t++)
            mma_bf16(oacc[t], aph[kc], &bvh[t >> 1][(t & 1) * 2]);
        #pragma unroll
        for (int t = 0; t < 4; t++)
            mma_bf16(oacc[t], apl[kc], &bvh[t >> 1][(t & 1) * 2]);
        #pragma unroll
        for (int t = 0; t < 4; t++)
            mma_bf16(oacc[t], aph[kc], &bvl[t >> 1][(t & 1) * 2]);
    }

    // ---- phase 6: store O (fp32, token-major) ----
    float* outbuf = (SHIFT == 0) ? g_attnT : g_attnT2;
    const int ntok0 = mt * 16 + (lane >> 2);
    const int cb = chq + dh * 32 + (lane & 3) * 2;
    #pragma unroll
    for (int half = 0; half < 2; half++) {
        int n = ntok0 + half * 8;
        int y = y0 + (n >> 3), x = x0 + (n & 7);
        if (SHIFT == 0 || ((unsigned)y < H_ && (unsigned)x < W_)) {
            float* op = outbuf + ((size_t)b * HW + (size_t)y * W_ + x) * CQ;
            #pragma unroll
            for (int t = 0; t < 4; t++) {
                float2 v;
                v.x = oacc[t][half * 2 + 0];
                v.y = oacc[t][half * 2 + 1];
                *(float2*)&op[cb + t * 8] = v;
            }
        }
    }
}

__global__ __launch_bounds__(256) void wattn_all_kernel()
{
    extern __shared__ char dynat[];
    if (blockIdx.x < 256)
        wattn_body<0, 16>(blockIdx.x, dynat);
    else
        wattn_body<4, 17>(blockIdx.x - 256, dynat);
}

// ---------------------------------------------------------------------------
extern "C" void kernel_launch(void* const* d_in, const int* in_sizes, int n_in,
                              void* d_out, int out_size)
{
    (void)in_sizes; (void)n_in; (void)out_size;
    const float* x      = (const float*)d_in[0];
    const float* w_qkv  = (const float*)d_in[1];
    const float* b_qkv  = (const float*)d_in[2];
    const float* w_head = (const float*)d_in[3];
    const float* b_head = (const float*)d_in[4];
    float* out = (float*)d_out;

    cudaFuncSetAttribute(gemm_bf16x3_kernel,
                         cudaFuncAttributeMaxDynamicSharedMemorySize, GEMM_SMEM);
    cudaFuncSetAttribute(wattn_all_kernel,
                         cudaFuncAttributeMaxDynamicSharedMemorySize, AT_SMEM);

    // 0a) split weights (device-side symbol selection)
    prep_w_kernel<<<(C3 * KDIM / 4 + 255) / 256, 256>>>(w_qkv, 0, C3 * KDIM / 4);
    prep_w_kernel<<<(CQ * KDIM / 4 + 255) / 256, 256>>>(w_head, 1, CQ * KDIM / 4);
    // 0b) transpose + split x -> g_xb_hi/lo [b][hw][c]
    {
        dim3 grid(HW / 32, CIN / 32, NB);
        transpose_x_kernel<<<grid, 256>>>(x);
    }
    // 1) qkv projection -> token-major q/k (bf16 split) + v (fp32)
    {
        dim3 grid(C3 / 128, HW / 128, NB);
        gemm_bf16x3_kernel<<<grid, 256, GEMM_SMEM>>>(b_qkv, nullptr, 0);
    }
    // 2+3) both window-attention branches, one launch (tensor-core)
    {
        dim3 grid(256 + 289, NH, NB);
        wattn_all_kernel<<<grid, 256, AT_SMEM>>>();
    }
    // 3b) sum branches + split to bf16 hi/lo
    sum_split_kernel<<<(int)((size_t)NB * HW * CQ / 4 / 256), 256>>>();
    // 4) out = w_head @ (x1+x2) + b_head  (M=384)
    {
        dim3 grid(CQ / 128, HW / 128, NB);
        gemm_bf16x3_kernel<<<grid, 256, GEMM_SMEM>>>(b_head, out, 1);
    }
}